// round 2
// baseline (speedup 1.0000x reference)
#include <cuda_runtime.h>

#define HDIM 50
#define TLEN 512
#define NBATCH 4096
#define BPT 4                  // batches per thread
#define NSLOT 8                // batch slots per CTA
#define NB (BPT*NSLOT)         // 32 batches per CTA
#define NTH (NSLOT*HDIM)       // 400 threads per CTA
#define NCTA (NBATCH/NB)       // 128 CTAs
#define KP 64                  // floats per k-row of h buffers: X[32] + Y[32]
#define HBUF (HDIM*KP)         // 3200 floats per h buffer

typedef unsigned long long u64;

__device__ __forceinline__ u64 pk2(float lo, float hi) {
    u64 r; asm("mov.b64 %0, {%1,%2};" : "=l"(r) : "f"(lo), "f"(hi)); return r;
}
__device__ __forceinline__ void upk2(u64 v, float& lo, float& hi) {
    asm("mov.b64 {%0,%1}, %2;" : "=f"(lo), "=f"(hi) : "l"(v));
}
// packed fp32x2 FMA (Blackwell 2x fp32 path; only reachable via PTX)
__device__ __forceinline__ u64 ffma2(u64 a, u64 b, u64 c) {
    u64 d; asm("fma.rn.f32x2 %0, %1, %2, %3;" : "=l"(d) : "l"(a), "l"(b), "l"(c)); return d;
}

__device__ __forceinline__ float sigf(float z) {
    return __fdividef(1.0f, 1.0f + __expf(-z));
}
__device__ __forceinline__ float tanhfast(float z) {
    return fmaf(2.0f, sigf(2.0f * z), -1.0f);
}

__device__ __forceinline__ void cellupd(u64 aif, u64 ago, float& c, float& h) {
    float zi, zf, zg, zo;
    upk2(aif, zi, zf);
    upk2(ago, zg, zo);
    float ig = sigf(zi);
    float fg = sigf(zf);
    float gg = tanhfast(zg);
    float og = sigf(zo);
    c = fmaf(fg, c, ig * gg);
    h = og * tanhfast(c);
}

// 4-gate matvec for unit u over K=50 duplicated-h values, 4 batches.
// Weights: 8 lanes share u -> LDS dedups to 64B/warp. h: X/Y rows 128B contiguous.
__device__ __forceinline__ void matvec_acc(const float* __restrict__ W,
                                           const float* __restrict__ hk,
                                           int u, int bslot,
                                           u64 aif[BPT], u64 ago[BPT]) {
    const ulonglong2* __restrict__ Wp = (const ulonglong2*)W;  // [(k*HDIM+u)] -> ((wi,wf),(wg,wo))
#pragma unroll 5
    for (int k = 0; k < HDIM; k++) {
        ulonglong2 w  = Wp[k * HDIM + u];
        ulonglong2 hx = *(const ulonglong2*)(hk + k * KP + 4 * bslot);        // (b0,b0),(b1,b1)
        ulonglong2 hy = *(const ulonglong2*)(hk + k * KP + 32 + 4 * bslot);   // (b2,b2),(b3,b3)
        aif[0] = ffma2(w.x, hx.x, aif[0]); ago[0] = ffma2(w.y, hx.x, ago[0]);
        aif[1] = ffma2(w.x, hx.y, aif[1]); ago[1] = ffma2(w.y, hx.y, ago[1]);
        aif[2] = ffma2(w.x, hy.x, aif[2]); ago[2] = ffma2(w.y, hy.x, ago[2]);
        aif[3] = ffma2(w.x, hy.y, aif[3]); ago[3] = ffma2(w.y, hy.y, ago[3]);
    }
}

// dynamic smem (floats):
//  W0  [50 k][50 u][4 g]   10000
//  W1i                     10000
//  W1h                     10000
//  h0d [2][HBUF]            6400
//  h1d [2][HBUF]            6400
//  xs  [2][NB]                64
#define SMEM_FLOATS (30000 + 2*HBUF*2 + 2*NB)

__global__ void __launch_bounds__(NTH, 1)
lstm_kernel(const float* __restrict__ x,
            const float* __restrict__ w_ih0, const float* __restrict__ w_hh0,
            const float* __restrict__ b_ih0, const float* __restrict__ b_hh0,
            const float* __restrict__ w_ih1, const float* __restrict__ w_hh1,
            const float* __restrict__ b_ih1, const float* __restrict__ b_hh1,
            const float* __restrict__ fc_w,  const float* __restrict__ fc_b,
            float* __restrict__ out) {
    extern __shared__ float smem[];
    float* W0  = smem;
    float* W1i = W0  + 4 * HDIM * HDIM;
    float* W1h = W1i + 4 * HDIM * HDIM;
    float* h0d = W1h + 4 * HDIM * HDIM;
    float* h1d = h0d + 2 * HBUF;
    float* xs  = h1d + 2 * HBUF;

    const int tid   = threadIdx.x;
    const int u     = tid / NSLOT;    // 8 lanes share a weight row -> broadcast
    const int bslot = tid % NSLOT;
    const int b0    = blockIdx.x * NB;

    // ---- stage weights into smem, re-laid-out [k][u][gate] ----
    for (int i = tid; i < 4 * HDIM * HDIM; i += NTH) {
        int r = i / HDIM;        // r = g*H + uu
        int k = i % HDIM;
        int g = r / HDIM;
        int uu = r % HDIM;
        int o = (k * HDIM + uu) * 4 + g;
        W0[o]  = w_hh0[i];
        W1i[o] = w_ih1[i];
        W1h[o] = w_hh1[i];
    }
    // zero all h buffers (h0d and h1d are contiguous)
    for (int i = tid; i < 4 * HBUF; i += NTH) h0d[i] = 0.0f;
    // stage x for t=0
    if (tid < NB) xs[tid] = x[(size_t)(b0 + tid) * TLEN + 0];

    // ---- per-thread constants ----
    u64 w0if = pk2(w_ih0[0 * HDIM + u], w_ih0[1 * HDIM + u]);
    u64 w0go = pk2(w_ih0[2 * HDIM + u], w_ih0[3 * HDIM + u]);
    u64 bias0if = pk2(b_ih0[0 * HDIM + u] + b_hh0[0 * HDIM + u],
                      b_ih0[1 * HDIM + u] + b_hh0[1 * HDIM + u]);
    u64 bias0go = pk2(b_ih0[2 * HDIM + u] + b_hh0[2 * HDIM + u],
                      b_ih0[3 * HDIM + u] + b_hh0[3 * HDIM + u]);
    u64 bias1if = pk2(b_ih1[0 * HDIM + u] + b_hh1[0 * HDIM + u],
                      b_ih1[1 * HDIM + u] + b_hh1[1 * HDIM + u]);
    u64 bias1go = pk2(b_ih1[2 * HDIM + u] + b_hh1[2 * HDIM + u],
                      b_ih1[3 * HDIM + u] + b_hh1[3 * HDIM + u]);

    float c0[BPT], c1[BPT], hn0[BPT], hn1[BPT];
#pragma unroll
    for (int b = 0; b < BPT; b++) { c0[b] = 0.0f; c1[b] = 0.0f; hn1[b] = 0.0f; }

    __syncthreads();

    int cur = 0;

    // ===== peeled phase p=0: only L0(0); recurrent h is zero but buffers are zeroed =====
    {
        const int nxt = 1;
        u64 aif0[BPT], ago0[BPT];
#pragma unroll
        for (int b = 0; b < BPT; b++) {
            float xv = xs[4 * bslot + b];
            u64 xp = pk2(xv, xv);
            aif0[b] = ffma2(w0if, xp, bias0if);
            ago0[b] = ffma2(w0go, xp, bias0go);
        }
        matvec_acc(W0, h0d, u, bslot, aif0, ago0);   // all zeros, keeps code uniform
#pragma unroll
        for (int b = 0; b < BPT; b++) cellupd(aif0[b], ago0[b], c0[b], hn0[b]);
        *(float4*)(h0d + nxt * HBUF + u * KP + 4 * bslot) =
            make_float4(hn0[0], hn0[0], hn0[1], hn0[1]);
        *(float4*)(h0d + nxt * HBUF + u * KP + 32 + 4 * bslot) =
            make_float4(hn0[2], hn0[2], hn0[3], hn0[3]);
        if (tid < NB) xs[NB + tid] = x[(size_t)(b0 + tid) * TLEN + 1];
        __syncthreads();
        cur = 1;
    }

    // ===== skewed main loop: phase p computes L0(p) and L1(p-1), ONE sync =====
    for (int p = 1; p < TLEN; p++) {
        const int nxt = cur ^ 1;

        // L0(p): x-term + recurrent over h0(p-1)
        u64 aif0[BPT], ago0[BPT];
#pragma unroll
        for (int b = 0; b < BPT; b++) {
            float xv = xs[cur * NB + 4 * bslot + b];
            u64 xp = pk2(xv, xv);
            aif0[b] = ffma2(w0if, xp, bias0if);
            ago0[b] = ffma2(w0go, xp, bias0go);
        }
        matvec_acc(W0, h0d + cur * HBUF, u, bslot, aif0, ago0);

        // L1(p-1): input h0(p-1), recurrent h1(p-2)
        u64 aif1[BPT], ago1[BPT];
#pragma unroll
        for (int b = 0; b < BPT; b++) { aif1[b] = bias1if; ago1[b] = bias1go; }
        matvec_acc(W1i, h0d + cur * HBUF, u, bslot, aif1, ago1);
        matvec_acc(W1h, h1d + cur * HBUF, u, bslot, aif1, ago1);

#pragma unroll
        for (int b = 0; b < BPT; b++) cellupd(aif0[b], ago0[b], c0[b], hn0[b]);
#pragma unroll
        for (int b = 0; b < BPT; b++) cellupd(aif1[b], ago1[b], c1[b], hn1[b]);

        *(float4*)(h0d + nxt * HBUF + u * KP + 4 * bslot) =
            make_float4(hn0[0], hn0[0], hn0[1], hn0[1]);
        *(float4*)(h0d + nxt * HBUF + u * KP + 32 + 4 * bslot) =
            make_float4(hn0[2], hn0[2], hn0[3], hn0[3]);
        *(float4*)(h1d + nxt * HBUF + u * KP + 4 * bslot) =
            make_float4(hn1[0], hn1[0], hn1[1], hn1[1]);
        *(float4*)(h1d + nxt * HBUF + u * KP + 32 + 4 * bslot) =
            make_float4(hn1[2], hn1[2], hn1[3], hn1[3]);

        if (tid < NB && (p + 1) < TLEN)
            xs[nxt * NB + tid] = x[(size_t)(b0 + tid) * TLEN + (p + 1)];

        __syncthreads();
        cur = nxt;
    }

    // ===== tail: L1(511) from h0(511)=h0d[cur], h1(510)=h1d[cur] =====
    {
        u64 aif1[BPT], ago1[BPT];
#pragma unroll
        for (int b = 0; b < BPT; b++) { aif1[b] = bias1if; ago1[b] = bias1go; }
        matvec_acc(W1i, h0d + cur * HBUF, u, bslot, aif1, ago1);
        matvec_acc(W1h, h1d + cur * HBUF, u, bslot, aif1, ago1);
#pragma unroll
        for (int b = 0; b < BPT; b++) cellupd(aif1[b], ago1[b], c1[b], hn1[b]);
    }

    __syncthreads();   // everyone done reading h0d before it's reused as scratch

    // ===== FC epilogue: out[b] = fc_w . h1_last[b] + fc_b =====
    {
        float fw = fc_w[u];
        *(float4*)(h0d + u * 32 + 4 * bslot) =
            make_float4(fw * hn1[0], fw * hn1[1], fw * hn1[2], fw * hn1[3]);
        __syncthreads();
        if (tid < NB) {
            float s = fc_b[0];
#pragma unroll 10
            for (int k = 0; k < HDIM; k++) s += h0d[k * 32 + tid];
            out[b0 + tid] = s;
        }
    }
}

extern "C" void kernel_launch(void* const* d_in, const int* in_sizes, int n_in,
                              void* d_out, int out_size) {
    const float* x     = (const float*)d_in[0];
    const float* w_ih0 = (const float*)d_in[1];
    const float* w_hh0 = (const float*)d_in[2];
    const float* b_ih0 = (const float*)d_in[3];
    const float* b_hh0 = (const float*)d_in[4];
    const float* w_ih1 = (const float*)d_in[5];
    const float* w_hh1 = (const float*)d_in[6];
    const float* b_ih1 = (const float*)d_in[7];
    const float* b_hh1 = (const float*)d_in[8];
    const float* fc_w  = (const float*)d_in[9];
    const float* fc_b  = (const float*)d_in[10];
    float* out = (float*)d_out;

    const size_t smem_bytes = SMEM_FLOATS * sizeof(float);
    cudaFuncSetAttribute(lstm_kernel, cudaFuncAttributeMaxDynamicSharedMemorySize,
                         (int)smem_bytes);
    lstm_kernel<<<NCTA, NTH, smem_bytes>>>(x, w_ih0, w_hh0, b_ih0, b_hh0,
                                           w_ih1, w_hh1, b_ih1, b_hh1,
                                           fc_w, fc_b, out);
}

// round 3
// speedup vs baseline: 1.4650x; 1.4650x over previous
#include <cuda_runtime.h>

#define HDIM 50
#define TLEN 512
#define NBATCH 4096
#define BPT 4                  // batches per thread
#define NSLOT 8                // batch slots per CTA
#define NB (BPT*NSLOT)         // 32 batches per CTA
#define NTH (NSLOT*HDIM)       // 400 threads per CTA
#define NCTA (NBATCH/NB)       // 128 CTAs
#define HP 36                  // h buffer pitch (floats) -> breaks bank conflicts

typedef unsigned long long u64;

__device__ __forceinline__ u64 pk2(float lo, float hi) {
    u64 r; asm("mov.b64 %0, {%1,%2};" : "=l"(r) : "f"(lo), "f"(hi)); return r;
}
__device__ __forceinline__ void upk2(u64 v, float& lo, float& hi) {
    asm("mov.b64 {%0,%1}, %2;" : "=f"(lo), "=f"(hi) : "l"(v));
}
// packed fp32x2 FMA (Blackwell 2x fp32 path; only reachable via PTX)
__device__ __forceinline__ u64 ffma2(u64 a, u64 b, u64 c) {
    u64 d; asm("fma.rn.f32x2 %0, %1, %2, %3;" : "=l"(d) : "l"(a), "l"(b), "l"(c)); return d;
}

__device__ __forceinline__ float sigf(float z) {
    return __fdividef(1.0f, 1.0f + __expf(-z));
}
__device__ __forceinline__ float tanhfast(float z) {
    // tanh(z) = 2*sigmoid(2z) - 1
    return fmaf(2.0f, sigf(2.0f * z), -1.0f);
}

// accumulate 4-gate matvec for unit u over K=50 source-h values, 4 batches
// mapping u=tid/8: 8 lanes share each weight row -> warp reads 4 rows = 64B (1 wf)
// h read: 8 distinct 16B chunks = 128B contiguous (1 wf)
__device__ __forceinline__ void matvec_acc(const float* __restrict__ W,
                                           const float* __restrict__ hbase,
                                           int u, int bslot,
                                           u64 aif[BPT], u64 ago[BPT]) {
    const ulonglong2* __restrict__ Wp = (const ulonglong2*)W;  // [k*HDIM + u] -> ((wi,wf),(wg,wo))
#pragma unroll 5
    for (int k = 0; k < HDIM; k++) {
        ulonglong2 w = Wp[k * HDIM + u];
        float4 h4 = *(const float4*)(hbase + k * HP + 4 * bslot);
        float hv0 = h4.x, hv1 = h4.y, hv2 = h4.z, hv3 = h4.w;
        u64 hp;
        hp = pk2(hv0, hv0); aif[0] = ffma2(w.x, hp, aif[0]); ago[0] = ffma2(w.y, hp, ago[0]);
        hp = pk2(hv1, hv1); aif[1] = ffma2(w.x, hp, aif[1]); ago[1] = ffma2(w.y, hp, ago[1]);
        hp = pk2(hv2, hv2); aif[2] = ffma2(w.x, hp, aif[2]); ago[2] = ffma2(w.y, hp, ago[2]);
        hp = pk2(hv3, hv3); aif[3] = ffma2(w.x, hp, aif[3]); ago[3] = ffma2(w.y, hp, ago[3]);
    }
}

__device__ __forceinline__ void cellupd(u64 aif, u64 ago, float& c, float& h) {
    float zi, zf, zg, zo;
    upk2(aif, zi, zf);
    upk2(ago, zg, zo);
    float ig = sigf(zi);
    float fg = sigf(zf);
    float gg = tanhfast(zg);
    float og = sigf(zo);
    c = fmaf(fg, c, ig * gg);
    h = og * tanhfast(c);
}

// dynamic smem layout (floats):
//  W0  [HDIM k][HDIM u][4 gates]      10000
//  W1i [HDIM k][HDIM u][4 gates]      10000
//  W1h [HDIM k][HDIM u][4 gates]      10000
//  h0b [2][HDIM][HP]                   3600
//  h1b [2][HDIM][HP]                   3600
//  xs  [2][NB]                           64
#define SMEM_FLOATS (30000 + 2*HDIM*HP*2 + 2*NB)

__global__ void __launch_bounds__(NTH, 1)
lstm_kernel(const float* __restrict__ x,
            const float* __restrict__ w_ih0, const float* __restrict__ w_hh0,
            const float* __restrict__ b_ih0, const float* __restrict__ b_hh0,
            const float* __restrict__ w_ih1, const float* __restrict__ w_hh1,
            const float* __restrict__ b_ih1, const float* __restrict__ b_hh1,
            const float* __restrict__ fc_w,  const float* __restrict__ fc_b,
            float* __restrict__ out) {
    extern __shared__ float smem[];
    float* W0  = smem;
    float* W1i = W0  + 4 * HDIM * HDIM;
    float* W1h = W1i + 4 * HDIM * HDIM;
    float* h0b = W1h + 4 * HDIM * HDIM;
    float* h1b = h0b + 2 * HDIM * HP;
    float* xs  = h1b + 2 * HDIM * HP;

    const int tid   = threadIdx.x;
    const int u     = tid / NSLOT;    // 8 lanes share each weight row
    const int bslot = tid % NSLOT;
    const int b0    = blockIdx.x * NB;

    // ---- stage weights into smem, re-laid-out [k][u][gate] ----
    for (int i = tid; i < 4 * HDIM * HDIM; i += NTH) {
        int r = i / HDIM;        // row in [4H, H] weight: r = g*H + uu
        int k = i % HDIM;
        int g = r / HDIM;
        int uu = r % HDIM;
        int o = (k * HDIM + uu) * 4 + g;
        W0[o]  = w_hh0[i];
        W1i[o] = w_ih1[i];
        W1h[o] = w_hh1[i];
    }
    // zero initial h buffers (buffer 0)
    for (int i = tid; i < HDIM * HP; i += NTH) {
        h0b[i] = 0.0f;
        h1b[i] = 0.0f;
    }
    // stage x for t=0
    if (tid < NB) xs[tid] = x[(size_t)(b0 + tid) * TLEN + 0];

    // ---- per-thread constants ----
    u64 w0if = pk2(w_ih0[0 * HDIM + u], w_ih0[1 * HDIM + u]);
    u64 w0go = pk2(w_ih0[2 * HDIM + u], w_ih0[3 * HDIM + u]);
    u64 bias0if = pk2(b_ih0[0 * HDIM + u] + b_hh0[0 * HDIM + u],
                      b_ih0[1 * HDIM + u] + b_hh0[1 * HDIM + u]);
    u64 bias0go = pk2(b_ih0[2 * HDIM + u] + b_hh0[2 * HDIM + u],
                      b_ih0[3 * HDIM + u] + b_hh0[3 * HDIM + u]);
    u64 bias1if = pk2(b_ih1[0 * HDIM + u] + b_hh1[0 * HDIM + u],
                      b_ih1[1 * HDIM + u] + b_hh1[1 * HDIM + u]);
    u64 bias1go = pk2(b_ih1[2 * HDIM + u] + b_hh1[2 * HDIM + u],
                      b_ih1[3 * HDIM + u] + b_hh1[3 * HDIM + u]);

    float c0[BPT], c1[BPT], hn0[BPT], hn1[BPT];
#pragma unroll
    for (int b = 0; b < BPT; b++) { c0[b] = 0.0f; c1[b] = 0.0f; hn1[b] = 0.0f; }

    __syncthreads();

    int cur = 0;
    for (int t = 0; t < TLEN; t++) {
        const int nxt = cur ^ 1;

        // ===== Phase A: layer 0 =====
        u64 aif[BPT], ago[BPT];
#pragma unroll
        for (int b = 0; b < BPT; b++) {
            float xv = xs[cur * NB + 4 * bslot + b];
            u64 xp = pk2(xv, xv);
            aif[b] = ffma2(w0if, xp, bias0if);
            ago[b] = ffma2(w0go, xp, bias0go);
        }
        matvec_acc(W0, h0b + cur * HDIM * HP, u, bslot, aif, ago);
#pragma unroll
        for (int b = 0; b < BPT; b++) cellupd(aif[b], ago[b], c0[b], hn0[b]);
        *(float4*)(h0b + nxt * HDIM * HP + u * HP + 4 * bslot) =
            make_float4(hn0[0], hn0[1], hn0[2], hn0[3]);
        __syncthreads();

        // ===== Phase B: layer 1 =====
#pragma unroll
        for (int b = 0; b < BPT; b++) { aif[b] = bias1if; ago[b] = bias1go; }
        matvec_acc(W1i, h0b + nxt * HDIM * HP, u, bslot, aif, ago);  // input = new h0
        matvec_acc(W1h, h1b + cur * HDIM * HP, u, bslot, aif, ago);  // recurrent h1
#pragma unroll
        for (int b = 0; b < BPT; b++) cellupd(aif[b], ago[b], c1[b], hn1[b]);
        *(float4*)(h1b + nxt * HDIM * HP + u * HP + 4 * bslot) =
            make_float4(hn1[0], hn1[1], hn1[2], hn1[3]);

        // stage x for next step
        if (tid < NB && (t + 1) < TLEN)
            xs[nxt * NB + tid] = x[(size_t)(b0 + tid) * TLEN + (t + 1)];

        __syncthreads();
        cur = nxt;
    }

    // ===== FC epilogue: out[b] = fc_w . h1_last[b] + fc_b =====
    // reuse h0b buffer 0 as reduction scratch: red[u][batch]
    float fw = fc_w[u];
    *(float4*)(h0b + u * HP + 4 * bslot) =
        make_float4(fw * hn1[0], fw * hn1[1], fw * hn1[2], fw * hn1[3]);
    __syncthreads();
    if (tid < NB) {
        float s = fc_b[0];
#pragma unroll 10
        for (int k = 0; k < HDIM; k++) s += h0b[k * HP + tid];
        out[b0 + tid] = s;
    }
}

extern "C" void kernel_launch(void* const* d_in, const int* in_sizes, int n_in,
                              void* d_out, int out_size) {
    const float* x     = (const float*)d_in[0];
    const float* w_ih0 = (const float*)d_in[1];
    const float* w_hh0 = (const float*)d_in[2];
    const float* b_ih0 = (const float*)d_in[3];
    const float* b_hh0 = (const float*)d_in[4];
    const float* w_ih1 = (const float*)d_in[5];
    const float* w_hh1 = (const float*)d_in[6];
    const float* b_ih1 = (const float*)d_in[7];
    const float* b_hh1 = (const float*)d_in[8];
    const float* fc_w  = (const float*)d_in[9];
    const float* fc_b  = (const float*)d_in[10];
    float* out = (float*)d_out;

    const size_t smem_bytes = SMEM_FLOATS * sizeof(float);
    cudaFuncSetAttribute(lstm_kernel, cudaFuncAttributeMaxDynamicSharedMemorySize,
                         (int)smem_bytes);
    lstm_kernel<<<NCTA, NTH, smem_bytes>>>(x, w_ih0, w_hh0, b_ih0, b_hh0,
                                           w_ih1, w_hh1, b_ih1, b_hh1,
                                           fc_w, fc_b, out);
}

// round 4
// speedup vs baseline: 1.5602x; 1.0650x over previous
#include <cuda_runtime.h>

#define HDIM 50
#define TLEN 512
#define NBATCH 4096
#define BPT 2                  // batches per thread
#define NSLOT 8                // batch slots per CTA
#define NB (BPT*NSLOT)         // 16 batches per CTA
#define NTH (NSLOT*HDIM)       // 400 threads per CTA
#define NCTA (NBATCH/NB)       // 256 CTAs -> 2 per SM on most SMs
#define HP 36                  // h buffer pitch (floats)
#define WMAT (4*HDIM*HDIM)     // 10000 floats per weight matrix

typedef unsigned long long u64;

// transposed weights, shared by all CTAs through L1: [m][ (k*HDIM+u)*4 + g ]
__device__ float Wt_g[3 * WMAT];

__device__ __forceinline__ u64 pk2(float lo, float hi) {
    u64 r; asm("mov.b64 %0, {%1,%2};" : "=l"(r) : "f"(lo), "f"(hi)); return r;
}
__device__ __forceinline__ void upk2(u64 v, float& lo, float& hi) {
    asm("mov.b64 {%0,%1}, %2;" : "=f"(lo), "=f"(hi) : "l"(v));
}
// packed fp32x2 FMA (Blackwell 2x fp32 path; only reachable via PTX)
__device__ __forceinline__ u64 ffma2(u64 a, u64 b, u64 c) {
    u64 d; asm("fma.rn.f32x2 %0, %1, %2, %3;" : "=l"(d) : "l"(a), "l"(b), "l"(c)); return d;
}

__device__ __forceinline__ float sigf(float z) {
    return __fdividef(1.0f, 1.0f + __expf(-z));
}
__device__ __forceinline__ float tanhfast(float z) {
    return fmaf(2.0f, sigf(2.0f * z), -1.0f);
}

__device__ __forceinline__ void cellupd(u64 aif, u64 ago, float& c, float& h) {
    float zi, zf, zg, zo;
    upk2(aif, zi, zf);
    upk2(ago, zg, zo);
    float ig = sigf(zi);
    float fg = sigf(zf);
    float gg = tanhfast(zg);
    float og = sigf(zo);
    c = fmaf(fg, c, ig * gg);
    h = og * tanhfast(c);
}

// 4-gate matvec for unit u over K=50 source-h values, 2 batches.
// Weights through L1 (identical across CTAs/steps -> always hit).
__device__ __forceinline__ void matvec_acc(const ulonglong2* __restrict__ Wp,
                                           const float* __restrict__ hbase,
                                           int u, int bslot,
                                           u64 aif[BPT], u64 ago[BPT]) {
#pragma unroll 10
    for (int k = 0; k < HDIM; k++) {
        ulonglong2 w = __ldg(&Wp[k * HDIM + u]);
        float2 h2 = *(const float2*)(hbase + k * HP + 2 * bslot);
        u64 hp;
        hp = pk2(h2.x, h2.x); aif[0] = ffma2(w.x, hp, aif[0]); ago[0] = ffma2(w.y, hp, ago[0]);
        hp = pk2(h2.y, h2.y); aif[1] = ffma2(w.x, hp, aif[1]); ago[1] = ffma2(w.y, hp, ago[1]);
    }
}

// prep: transpose the three [4H, H] row-major matrices into [k][u][gate]
__global__ void transpose_kernel(const float* __restrict__ w_hh0,
                                 const float* __restrict__ w_ih1,
                                 const float* __restrict__ w_hh1) {
    int idx = blockIdx.x * blockDim.x + threadIdx.x;
    if (idx >= WMAT) return;
    int r = idx / HDIM;        // r = g*H + uu
    int k = idx % HDIM;
    int g = r / HDIM;
    int uu = r % HDIM;
    int o = (k * HDIM + uu) * 4 + g;
    Wt_g[o]            = w_hh0[idx];
    Wt_g[WMAT + o]     = w_ih1[idx];
    Wt_g[2 * WMAT + o] = w_hh1[idx];
}

// dynamic smem (floats):
//  h0b [2][HDIM][HP]   3600
//  h1b [2][HDIM][HP]   3600
//  xs  [2][NB]           32
#define SMEM_FLOATS (2*HDIM*HP*2 + 2*NB)

__global__ void __launch_bounds__(NTH, 2)
lstm_kernel(const float* __restrict__ x,
            const float* __restrict__ w_ih0, const float* __restrict__ b_ih0,
            const float* __restrict__ b_hh0,
            const float* __restrict__ b_ih1, const float* __restrict__ b_hh1,
            const float* __restrict__ fc_w,  const float* __restrict__ fc_b,
            float* __restrict__ out) {
    extern __shared__ float smem[];
    float* h0b = smem;
    float* h1b = h0b + 2 * HDIM * HP;
    float* xs  = h1b + 2 * HDIM * HP;

    const int tid   = threadIdx.x;
    const int u     = tid % HDIM;
    const int bslot = tid / HDIM;
    const int b0    = blockIdx.x * NB;

    const ulonglong2* W0  = (const ulonglong2*)(Wt_g);
    const ulonglong2* W1i = (const ulonglong2*)(Wt_g + WMAT);
    const ulonglong2* W1h = (const ulonglong2*)(Wt_g + 2 * WMAT);

    // zero initial h buffers (buffer 0)
    for (int i = tid; i < HDIM * HP; i += NTH) {
        h0b[i] = 0.0f;
        h1b[i] = 0.0f;
    }
    // stage x for t=0
    if (tid < NB) xs[tid] = x[(size_t)(b0 + tid) * TLEN + 0];

    // ---- per-thread constants ----
    u64 w0if = pk2(w_ih0[0 * HDIM + u], w_ih0[1 * HDIM + u]);
    u64 w0go = pk2(w_ih0[2 * HDIM + u], w_ih0[3 * HDIM + u]);
    u64 bias0if = pk2(b_ih0[0 * HDIM + u] + b_hh0[0 * HDIM + u],
                      b_ih0[1 * HDIM + u] + b_hh0[1 * HDIM + u]);
    u64 bias0go = pk2(b_ih0[2 * HDIM + u] + b_hh0[2 * HDIM + u],
                      b_ih0[3 * HDIM + u] + b_hh0[3 * HDIM + u]);
    u64 bias1if = pk2(b_ih1[0 * HDIM + u] + b_hh1[0 * HDIM + u],
                      b_ih1[1 * HDIM + u] + b_hh1[1 * HDIM + u]);
    u64 bias1go = pk2(b_ih1[2 * HDIM + u] + b_hh1[2 * HDIM + u],
                      b_ih1[3 * HDIM + u] + b_hh1[3 * HDIM + u]);

    float c0[BPT], c1[BPT], hn0[BPT], hn1[BPT];
#pragma unroll
    for (int b = 0; b < BPT; b++) { c0[b] = 0.0f; c1[b] = 0.0f; hn1[b] = 0.0f; }

    __syncthreads();

    int cur = 0;
    for (int t = 0; t < TLEN; t++) {
        const int nxt = cur ^ 1;

        // ===== Phase A: layer 0 =====
        u64 aif[BPT], ago[BPT];
#pragma unroll
        for (int b = 0; b < BPT; b++) {
            float xv = xs[cur * NB + 2 * bslot + b];
            u64 xp = pk2(xv, xv);
            aif[b] = ffma2(w0if, xp, bias0if);
            ago[b] = ffma2(w0go, xp, bias0go);
        }
        matvec_acc(W0, h0b + cur * HDIM * HP, u, bslot, aif, ago);
#pragma unroll
        for (int b = 0; b < BPT; b++) cellupd(aif[b], ago[b], c0[b], hn0[b]);
        *(float2*)(h0b + nxt * HDIM * HP + u * HP + 2 * bslot) =
            make_float2(hn0[0], hn0[1]);
        __syncthreads();

        // ===== Phase B: layer 1 =====
#pragma unroll
        for (int b = 0; b < BPT; b++) { aif[b] = bias1if; ago[b] = bias1go; }
        matvec_acc(W1i, h0b + nxt * HDIM * HP, u, bslot, aif, ago);  // input = new h0
        matvec_acc(W1h, h1b + cur * HDIM * HP, u, bslot, aif, ago);  // recurrent h1
#pragma unroll
        for (int b = 0; b < BPT; b++) cellupd(aif[b], ago[b], c1[b], hn1[b]);
        *(float2*)(h1b + nxt * HDIM * HP + u * HP + 2 * bslot) =
            make_float2(hn1[0], hn1[1]);

        // stage x for next step
        if (tid < NB && (t + 1) < TLEN)
            xs[nxt * NB + tid] = x[(size_t)(b0 + tid) * TLEN + (t + 1)];

        __syncthreads();
        cur = nxt;
    }

    // ===== FC epilogue: out[b] = fc_w . h1_last[b] + fc_b =====
    // reuse h0b as reduction scratch: red[u][batch], pitch 18 to avoid conflicts
    float fw = fc_w[u];
    *(float2*)(h0b + u * 18 + 2 * bslot) = make_float2(fw * hn1[0], fw * hn1[1]);
    __syncthreads();
    if (tid < NB) {
        float s = fc_b[0];
#pragma unroll 10
        for (int k = 0; k < HDIM; k++) s += h0b[k * 18 + tid];
        out[b0 + tid] = s;
    }
}

extern "C" void kernel_launch(void* const* d_in, const int* in_sizes, int n_in,
                              void* d_out, int out_size) {
    const float* x     = (const float*)d_in[0];
    const float* w_ih0 = (const float*)d_in[1];
    const float* w_hh0 = (const float*)d_in[2];
    const float* b_ih0 = (const float*)d_in[3];
    const float* b_hh0 = (const float*)d_in[4];
    const float* w_ih1 = (const float*)d_in[5];
    const float* w_hh1 = (const float*)d_in[6];
    const float* b_ih1 = (const float*)d_in[7];
    const float* b_hh1 = (const float*)d_in[8];
    const float* fc_w  = (const float*)d_in[9];
    const float* fc_b  = (const float*)d_in[10];
    float* out = (float*)d_out;

    transpose_kernel<<<(WMAT + 255) / 256, 256>>>(w_hh0, w_ih1, w_hh1);

    const size_t smem_bytes = SMEM_FLOATS * sizeof(float);
    lstm_kernel<<<NCTA, NTH, smem_bytes>>>(x, w_ih0, b_ih0, b_hh0,
                                           b_ih1, b_hh1, fc_w, fc_b, out);
}

// round 5
// speedup vs baseline: 1.9612x; 1.2570x over previous
#include <cuda_runtime.h>

#define HDIM 50
#define TLEN 512
#define NBATCH 4096
#define LANES 32               // batches per CTA (= lanes per warp)
#define UPT 5                  // units per thread
#define UG 10                  // unit groups (warps per CTA)
#define NTH (LANES*UG)         // 320 threads
#define NCTA (NBATCH/LANES)    // 128 CTAs
#define WSZ (4*HDIM*HDIM)      // 10000 floats per weight matrix

typedef unsigned long long u64;

__device__ __forceinline__ u64 pk2(float lo, float hi) {
    u64 r; asm("mov.b64 %0, {%1,%2};" : "=l"(r) : "f"(lo), "f"(hi)); return r;
}
__device__ __forceinline__ void upk2(u64 v, float& lo, float& hi) {
    asm("mov.b64 {%0,%1}, %2;" : "=f"(lo), "=f"(hi) : "l"(v));
}
// packed fp32x2 FMA (Blackwell 2x fp32 path; only reachable via PTX)
__device__ __forceinline__ u64 ffma2(u64 a, u64 b, u64 c) {
    u64 d; asm("fma.rn.f32x2 %0, %1, %2, %3;" : "=l"(d) : "l"(a), "l"(b), "l"(c)); return d;
}

__device__ __forceinline__ float sigf(float z) {
    return __fdividef(1.0f, 1.0f + __expf(-z));
}
__device__ __forceinline__ float tanhfast(float z) {
    return fmaf(2.0f, sigf(2.0f * z), -1.0f);
}

__device__ __forceinline__ void cellupd(u64 aif, u64 ago, float& c, float& h) {
    float zi, zf, zg, zo;
    upk2(aif, zi, zf);
    upk2(ago, zg, zo);
    float ig = sigf(zi);
    float fg = sigf(zf);
    float gg = tanhfast(zg);
    float og = sigf(zo);
    c = fmaf(fg, c, ig * gg);
    h = og * tanhfast(c);
}

// smem layout (float offsets):
//  W0  [u][k][4g]  10000   (ulonglong2 rows, warp-uniform broadcast reads)
//  W1i             10000
//  W1h             10000
//  h0s [50][32]     1600   (coalesced [k][lane])
//  h1s [50][32]     1600
//  xs  [32]           32
//  bA  u64[2][50]    200   (layer0 combined biases, pairs (i,f)|(g,o))
//  bB  u64[2][50]    200
//  w0t u64[2][50]    200   (layer0 input weights, pairs)
#define SM_W0   0
#define SM_W1I  10000
#define SM_W1H  20000
#define SM_H0   30000
#define SM_H1   31600
#define SM_XS   33200
#define SM_BA   33232
#define SM_BB   33432
#define SM_W0T  33632
#define SM_TOT  33832

__global__ void __launch_bounds__(NTH, 1)
lstm_kernel(const float* __restrict__ x,
            const float* __restrict__ w_ih0, const float* __restrict__ w_hh0,
            const float* __restrict__ b_ih0, const float* __restrict__ b_hh0,
            const float* __restrict__ w_ih1, const float* __restrict__ w_hh1,
            const float* __restrict__ b_ih1, const float* __restrict__ b_hh1,
            const float* __restrict__ fc_w,  const float* __restrict__ fc_b,
            float* __restrict__ out) {
    extern __shared__ float smem[];
    float* hs0 = smem + SM_H0;
    float* hs1 = smem + SM_H1;
    float* xs  = smem + SM_XS;

    const int tid  = threadIdx.x;
    const int lane = tid & 31;        // batch within CTA
    const int grp  = tid >> 5;        // unit group
    const int u0   = grp * UPT;
    const int b0   = blockIdx.x * LANES;

    // ---- stage weights transposed: [u][k][4 gates] ----
    for (int i = tid; i < WSZ; i += NTH) {
        int r = i / HDIM;             // r = g*H + uu
        int k = i % HDIM;
        int g = r / HDIM;
        int uu = r % HDIM;
        int o = (uu * HDIM + k) * 4 + g;
        smem[SM_W0  + o] = w_hh0[i];
        smem[SM_W1I + o] = w_ih1[i];
        smem[SM_W1H + o] = w_hh1[i];
    }
    // ---- stage biases / layer0 input weights as gate-pair u64 tables ----
    if (tid < HDIM) {
        int u = tid;
        u64* bA  = (u64*)(smem + SM_BA);
        u64* bB  = (u64*)(smem + SM_BB);
        u64* w0t = (u64*)(smem + SM_W0T);
#pragma unroll
        for (int p = 0; p < 2; p++) {
            int g0 = 2 * p, g1 = 2 * p + 1;
            bA[p * HDIM + u]  = pk2(b_ih0[g0 * HDIM + u] + b_hh0[g0 * HDIM + u],
                                    b_ih0[g1 * HDIM + u] + b_hh0[g1 * HDIM + u]);
            bB[p * HDIM + u]  = pk2(b_ih1[g0 * HDIM + u] + b_hh1[g0 * HDIM + u],
                                    b_ih1[g1 * HDIM + u] + b_hh1[g1 * HDIM + u]);
            w0t[p * HDIM + u] = pk2(w_ih0[g0 * HDIM + u], w_ih0[g1 * HDIM + u]);
        }
    }
    if (tid < LANES) xs[tid] = x[(size_t)(b0 + tid) * TLEN];
    __syncthreads();

    const ulonglong2* W0p  = (const ulonglong2*)(smem + SM_W0);
    const ulonglong2* W1ip = (const ulonglong2*)(smem + SM_W1I);
    const ulonglong2* W1hp = (const ulonglong2*)(smem + SM_W1H);
    const u64* bAp  = (const u64*)(smem + SM_BA);
    const u64* bBp  = (const u64*)(smem + SM_BB);
    const u64* w0tp = (const u64*)(smem + SM_W0T);

    // register-resident h state for this lane's batch
    float h0r[HDIM], h1r[HDIM];
#pragma unroll
    for (int k = 0; k < HDIM; k++) { h0r[k] = 0.0f; h1r[k] = 0.0f; }
    float c0[UPT], c1[UPT], hn1[UPT];
#pragma unroll
    for (int j = 0; j < UPT; j++) { c0[j] = 0.0f; c1[j] = 0.0f; hn1[j] = 0.0f; }

#pragma unroll 1
    for (int t = 0; t < TLEN; t++) {
        // ===== Phase A: layer 0 over h0r = h0(t-1) =====
        float xv = xs[lane];
        u64 xp = pk2(xv, xv);
        u64 aif[UPT], ago[UPT];
#pragma unroll
        for (int j = 0; j < UPT; j++) {
            aif[j] = ffma2(w0tp[u0 + j],        xp, bAp[u0 + j]);
            ago[j] = ffma2(w0tp[HDIM + u0 + j], xp, bAp[HDIM + u0 + j]);
        }
#pragma unroll
        for (int k = 0; k < HDIM; k++) {
            u64 hp = pk2(h0r[k], h0r[k]);
#pragma unroll
            for (int j = 0; j < UPT; j++) {
                ulonglong2 w = W0p[(u0 + j) * HDIM + k];
                aif[j] = ffma2(w.x, hp, aif[j]);
                ago[j] = ffma2(w.y, hp, ago[j]);
            }
        }
#pragma unroll
        for (int j = 0; j < UPT; j++) {
            float hn;
            cellupd(aif[j], ago[j], c0[j], hn);
            hs0[(u0 + j) * LANES + lane] = hn;
        }
        __syncthreads();
        // reload full h0(t) into registers (coalesced)
#pragma unroll
        for (int k = 0; k < HDIM; k++) h0r[k] = hs0[k * LANES + lane];

        // ===== Phase B: layer 1 over h0(t) + h1(t-1) =====
#pragma unroll
        for (int j = 0; j < UPT; j++) {
            aif[j] = bBp[u0 + j];
            ago[j] = bBp[HDIM + u0 + j];
        }
#pragma unroll
        for (int k = 0; k < HDIM; k++) {
            u64 hp0 = pk2(h0r[k], h0r[k]);
            u64 hp1 = pk2(h1r[k], h1r[k]);
#pragma unroll
            for (int j = 0; j < UPT; j++) {
                ulonglong2 wi = W1ip[(u0 + j) * HDIM + k];
                aif[j] = ffma2(wi.x, hp0, aif[j]);
                ago[j] = ffma2(wi.y, hp0, ago[j]);
                ulonglong2 wh = W1hp[(u0 + j) * HDIM + k];
                aif[j] = ffma2(wh.x, hp1, aif[j]);
                ago[j] = ffma2(wh.y, hp1, ago[j]);
            }
        }
#pragma unroll
        for (int j = 0; j < UPT; j++) {
            cellupd(aif[j], ago[j], c1[j], hn1[j]);
            hs1[(u0 + j) * LANES + lane] = hn1[j];
        }
        // stage x(t+1)
        if (tid < LANES && (t + 1) < TLEN)
            xs[tid] = x[(size_t)(b0 + tid) * TLEN + (t + 1)];
        __syncthreads();
        // reload full h1(t) into registers
#pragma unroll
        for (int k = 0; k < HDIM; k++) h1r[k] = hs1[k * LANES + lane];
    }

    // ===== FC epilogue: out[b] = fc_w . h1(T-1)[b] + fc_b =====
    {
        float p = 0.0f;
#pragma unroll
        for (int j = 0; j < UPT; j++) p += fc_w[u0 + j] * hn1[j];
        __syncthreads();                     // done with hs0 as h-buffer
        hs0[grp * LANES + lane] = p;         // partial per (grp, batch)
        __syncthreads();
        if (tid < LANES) {
            float s = fc_b[0];
#pragma unroll
            for (int g = 0; g < UG; g++) s += hs0[g * LANES + tid];
            out[b0 + tid] = s;
        }
    }
}

extern "C" void kernel_launch(void* const* d_in, const int* in_sizes, int n_in,
                              void* d_out, int out_size) {
    const float* x     = (const float*)d_in[0];
    const float* w_ih0 = (const float*)d_in[1];
    const float* w_hh0 = (const float*)d_in[2];
    const float* b_ih0 = (const float*)d_in[3];
    const float* b_hh0 = (const float*)d_in[4];
    const float* w_ih1 = (const float*)d_in[5];
    const float* w_hh1 = (const float*)d_in[6];
    const float* b_ih1 = (const float*)d_in[7];
    const float* b_hh1 = (const float*)d_in[8];
    const float* fc_w  = (const float*)d_in[9];
    const float* fc_b  = (const float*)d_in[10];
    float* out = (float*)d_out;

    const size_t smem_bytes = SM_TOT * sizeof(float);
    cudaFuncSetAttribute(lstm_kernel, cudaFuncAttributeMaxDynamicSharedMemorySize,
                         (int)smem_bytes);
    lstm_kernel<<<NCTA, NTH, smem_bytes>>>(x, w_ih0, w_hh0, b_ih0, b_hh0,
                                           w_ih1, w_hh1, b_ih1, b_hh1,
                                           fc_w, fc_b, out);
}